// round 9
// baseline (speedup 1.0000x reference)
#include <cuda_runtime.h>
#include <climits>

// ---- problem-size caps (ref: N=100000, E=1600000, G=512, F=128) ----
#define MAXN 131072
#define MAXE 2000000
#define NSM  148
#define SCAN_TB 1024

// scratch (no cudaMalloc allowed)
__device__ float  g_dot[MAXN];    // x@W per node
__device__ int    g_cnt[MAXN];    // in-degree count (deg = cnt + 1)
__device__ int    g_cur[MAXN];    // bump cursors for CSR place
__device__ float  g_dis[MAXN];    // deg^-1/2 (final output scaling)
__device__ float2 g_buf[4][MAXN]; // hop buffers {t, s}; gather computes t*s
__device__ int    g_bsum[256];    // scan block partials
__device__ int2   g_csr[MAXE];    // col-grouped edges {row, col}

#if defined(__CUDA_ARCH__) && (__CUDA_ARCH__ >= 900)
#define GRID_DEP_SYNC() cudaGridDependencySynchronize()
#else
#define GRID_DEP_SYNC()
#endif

// ---------------------------------------------------------------------------
// Fused preamble: GEMV blocks + degree-count blocks
// ---------------------------------------------------------------------------
__global__ void k_pre(const float* __restrict__ x, const float* __restrict__ W,
                      const int* __restrict__ col,
                      int n, int F, int E, int nGemv) {
    int lane = threadIdx.x & 31;
    if (blockIdx.x < nGemv) {
        int warp   = (blockIdx.x * blockDim.x + threadIdx.x) >> 5;
        int nwarps = (nGemv * blockDim.x) >> 5;
        if (F == 128) {
            float4 wv = *reinterpret_cast<const float4*>(W + lane * 4);
            for (int node = warp; node < n; node += nwarps) {
                float4 xv = *reinterpret_cast<const float4*>(x + (size_t)node * 128 + lane * 4);
                float acc = xv.x * wv.x + xv.y * wv.y + xv.z * wv.z + xv.w * wv.w;
                #pragma unroll
                for (int o = 16; o; o >>= 1) acc += __shfl_xor_sync(0xffffffffu, acc, o);
                if (lane == 0) g_dot[node] = acc;
            }
        } else {
            for (int node = warp; node < n; node += nwarps) {
                const float* xr = x + (size_t)node * F;
                float acc = 0.0f;
                for (int j = lane; j < F; j += 32) acc += xr[j] * W[j];
                #pragma unroll
                for (int o = 16; o; o >>= 1) acc += __shfl_xor_sync(0xffffffffu, acc, o);
                if (lane == 0) g_dot[node] = acc;
            }
        }
    } else {
        int tid = (blockIdx.x - nGemv) * blockDim.x + threadIdx.x;
        int nth = (gridDim.x - nGemv) * blockDim.x;
        int E4  = E >> 2;
        for (int q = tid; q < E4; q += nth) {
            int4 c = reinterpret_cast<const int4*>(col)[q];
            atomicAdd(&g_cnt[c.x], 1);
            atomicAdd(&g_cnt[c.y], 1);
            atomicAdd(&g_cnt[c.z], 1);
            atomicAdd(&g_cnt[c.w], 1);
        }
        if (tid == 0) for (int e = E4 << 2; e < E; e++) atomicAdd(&g_cnt[col[e]], 1);
    }
}

// ---- scan phase A: per-block totals of g_cnt ----
__global__ void k_scanA(int n) {
    GRID_DEP_SYNC();
    int i = blockIdx.x * SCAN_TB + threadIdx.x;
    int lane = threadIdx.x & 31;
    int warp = threadIdx.x >> 5;
    int v = (i < n) ? g_cnt[i] : 0;
    #pragma unroll
    for (int o = 16; o; o >>= 1) v += __shfl_xor_sync(0xffffffffu, v, o);
    __shared__ int sp[SCAN_TB / 32];
    if (lane == 0) sp[warp] = v;
    __syncthreads();
    if (threadIdx.x < 32) {
        int s = (threadIdx.x < SCAN_TB / 32) ? sp[threadIdx.x] : 0;
        #pragma unroll
        for (int o = 16; o; o >>= 1) s += __shfl_xor_sync(0xffffffffu, s, o);
        if (threadIdx.x == 0) g_bsum[blockIdx.x] = s;
    }
}

// ---- scan phase B: exclusive scan of block totals (nA <= 128) ----
__global__ void k_scanB(int nA) {
    GRID_DEP_SYNC();
    int tid  = threadIdx.x;
    int lane = tid & 31;
    int warp = tid >> 5;
    int v0 = (tid < nA) ? g_bsum[tid] : 0;
    int t = v0;
    #pragma unroll
    for (int o = 1; o < 32; o <<= 1) {
        int u = __shfl_up_sync(0xffffffffu, t, o);
        if (lane >= o) t += u;
    }
    __shared__ int wsum[4];
    if (lane == 31) wsum[warp] = t;
    __syncthreads();
    if (warp == 0 && lane < 4) {
        int w = wsum[lane];
        #pragma unroll
        for (int o = 1; o < 4; o <<= 1) {
            int u = __shfl_up_sync(0xFu, w, o);
            if (lane >= o) w += u;
        }
        wsum[lane] = w;
    }
    __syncthreads();
    int off = (warp > 0) ? wsum[warp - 1] : 0;
    g_bsum[tid] = t + off - v0;     // exclusive
}

// ---- scan phase C (+ fused scale/init): per-node cursor + hop buffers ----
__global__ void k_scanC(int n) {
    GRID_DEP_SYNC();
    int i    = blockIdx.x * SCAN_TB + threadIdx.x;
    int lane = threadIdx.x & 31;
    int warp = threadIdx.x >> 5;
    int cnt = (i < n) ? g_cnt[i] : 0;
    int t = cnt;
    #pragma unroll
    for (int o = 1; o < 32; o <<= 1) {
        int u = __shfl_up_sync(0xffffffffu, t, o);
        if (lane >= o) t += u;
    }
    __shared__ int sp[SCAN_TB / 32];
    if (lane == 31) sp[warp] = t;
    __syncthreads();
    if (threadIdx.x < 32) {
        int w = (threadIdx.x < SCAN_TB / 32) ? sp[threadIdx.x] : 0;
        #pragma unroll
        for (int o = 1; o < 32; o <<= 1) {
            int u = __shfl_up_sync(0xffffffffu, w, o);
            if ((threadIdx.x & 31) >= o) w += u;
        }
        sp[threadIdx.x] = w;
    }
    __syncthreads();
    int woff = (warp > 0) ? sp[warp - 1] : 0;
    if (i < n) {
        g_cur[i] = g_bsum[blockIdx.x] + woff + t - cnt;   // exclusive start
        float deg  = (float)(cnt + 1);                    // +1 self-loop
        float dinv = __frcp_rn(deg);
        float dis  = rsqrtf(deg);
        g_dis[i]    = dis;
        g_buf[0][i] = make_float2(g_dot[i], dis);
        g_buf[1][i] = make_float2(0.0f, dinv);
        g_buf[2][i] = make_float2(0.0f, dinv);
        g_buf[3][i] = make_float2(0.0f, 0.0f);
    }
}

// ---- CSR place: g_csr[bump(col)] = {row, col} ----
__global__ void k_place(const int* __restrict__ row, const int* __restrict__ col, int E) {
    GRID_DEP_SYNC();
    int tid = blockIdx.x * blockDim.x + threadIdx.x;
    int nth = gridDim.x * blockDim.x;
    int E4  = E >> 2;
    for (int q = tid; q < E4; q += nth) {
        int4 r = reinterpret_cast<const int4*>(row)[q];
        int4 c = reinterpret_cast<const int4*>(col)[q];
        int p0 = atomicAdd(&g_cur[c.x], 1);
        int p1 = atomicAdd(&g_cur[c.y], 1);
        int p2 = atomicAdd(&g_cur[c.z], 1);
        int p3 = atomicAdd(&g_cur[c.w], 1);
        g_csr[p0] = make_int2(r.x, c.x);
        g_csr[p1] = make_int2(r.y, c.y);
        g_csr[p2] = make_int2(r.z, c.z);
        g_csr[p3] = make_int2(r.w, c.w);
    }
    if (tid == 0) {
        for (int e = E4 << 2; e < E; e++) {
            int p = atomicAdd(&g_cur[col[e]], 1);
            g_csr[p] = make_int2(row[e], col[e]);
        }
    }
}

// ---- one hop over col-grouped edges: segmented warp-aggregated scatter ----
template<int SRC>
__global__ void k_hop(int E, int n) {
    GRID_DEP_SYNC();
    const float2* __restrict__ src = g_buf[SRC];
    float2*       __restrict__ dst = g_buf[SRC + 1];
    int tid  = blockIdx.x * blockDim.x + threadIdx.x;
    int nth  = gridDim.x * blockDim.x;
    int lane = threadIdx.x & 31;
    int gw   = tid >> 5;
    int nw   = nth >> 5;
    int nchunk = (E + 63) >> 6;   // 64 edges per warp-iteration

    for (int ch = gw; ch < nchunk; ch += nw) {
        int e0 = ch * 64 + lane;
        int e1 = e0 + 32;
        bool v0 = e0 < E, v1 = e1 < E;
        int2 rc0 = v0 ? g_csr[e0] : make_int2(0, INT_MAX);
        int2 rc1 = v1 ? g_csr[e1] : make_int2(0, INT_MAX);
        float2 a0 = v0 ? __ldg(&src[rc0.x]) : make_float2(0.0f, 0.0f);
        float2 a1 = v1 ? __ldg(&src[rc1.x]) : make_float2(0.0f, 0.0f);
        float s0 = a0.x * a0.y;
        float s1 = a1.x * a1.y;
        int c0 = rc0.y, c1 = rc1.y;
        // segmented sums (cols nondecreasing within each 32-edge window)
        #pragma unroll
        for (int o = 1; o < 32; o <<= 1) {
            float t0 = __shfl_down_sync(0xffffffffu, s0, o);
            int   u0 = __shfl_down_sync(0xffffffffu, c0, o);
            float t1 = __shfl_down_sync(0xffffffffu, s1, o);
            int   u1 = __shfl_down_sync(0xffffffffu, c1, o);
            if (lane + o < 32) {
                if (u0 == c0) s0 += t0;
                if (u1 == c1) s1 += t1;
            }
        }
        int p0 = __shfl_up_sync(0xffffffffu, c0, 1);
        int p1 = __shfl_up_sync(0xffffffffu, c1, 1);
        if (v0 && (lane == 0 || p0 != c0)) atomicAdd(&dst[c0].x, s0);
        if (v1 && (lane == 0 || p1 != c1)) atomicAdd(&dst[c1].x, s1);
    }
    // self-loop term (coalesced)
    for (int i = tid; i < n; i += nth) {
        float2 a = src[i];
        atomicAdd(&dst[i].x, a.x * a.y);
    }
}

// ---- fused scatter-mean + output: block g owns graph g (batch sorted) ----
__global__ void k_out(const int* __restrict__ batch, const float* __restrict__ bias,
                      float* __restrict__ out, int n) {
    GRID_DEP_SYNC();
    __shared__ int s_lo, s_hi;
    __shared__ float s_part[8];
    int g = blockIdx.x;

    if (threadIdx.x < 2) {
        int target = g + threadIdx.x;
        int lo = 0, hi = n;
        while (lo < hi) {
            int mid = (lo + hi) >> 1;
            if (batch[mid] < target) lo = mid + 1; else hi = mid;
        }
        if (threadIdx.x == 0) s_lo = lo; else s_hi = lo;
    }
    __syncthreads();

    int lo = s_lo, hi = s_hi;
    float local = 0.0f;
    for (int i = lo + threadIdx.x; i < hi; i += blockDim.x)
        local += g_dis[i] * g_buf[3][i].x;

    #pragma unroll
    for (int o = 16; o; o >>= 1) local += __shfl_xor_sync(0xffffffffu, local, o);
    int warp = threadIdx.x >> 5;
    if ((threadIdx.x & 31) == 0) s_part[warp] = local;
    __syncthreads();
    if (threadIdx.x == 0) {
        float sum = 0.0f;
        #pragma unroll
        for (int w = 0; w < 8; w++) sum += s_part[w];
        int c = hi - lo;
        out[g] = (c > 0) ? (sum / (float)c + bias[0]) : 0.0f;
    }
}

// ---------------------------------------------------------------------------
extern "C" void kernel_launch(void* const* d_in, const int* in_sizes, int n_in,
                              void* d_out, int out_size) {
    const float* x     = (const float*)d_in[0];
    const float* W     = (const float*)d_in[1];
    const float* b     = (const float*)d_in[2];
    const int*   ei    = (const int*)d_in[3];
    const int*   batch = (const int*)d_in[4];

    int F = in_sizes[1];
    int n = in_sizes[4];
    int E = in_sizes[3] / 2;
    int G = out_size;

    const int* row = ei;
    const int* col = ei + E;

    const int TB = 256;
    auto nbk = [](int v, int tb) { return (v + tb - 1) / tb; };

    void* p_cnt;
    cudaGetSymbolAddress(&p_cnt, g_cnt);
    cudaMemsetAsync(p_cnt, 0, (size_t)n * sizeof(int));

    cudaLaunchAttribute pdlAttr[1];
    pdlAttr[0].id = cudaLaunchAttributeProgrammaticStreamSerialization;
    pdlAttr[0].val.programmaticStreamSerializationAllowed = 1;

    int nGemv = NSM * 4;
    int nDeg  = NSM * 4;
    k_pre<<<nGemv + nDeg, TB>>>(x, W, col, n, F, E, nGemv);

    {
        cudaLaunchConfig_t cfg = {};
        cfg.attrs = pdlAttr;
        cfg.numAttrs = 1;

        int nA = nbk(n, SCAN_TB);   // <= 128 for MAXN
        cfg.blockDim = dim3(SCAN_TB, 1, 1);
        cfg.gridDim  = dim3(nA, 1, 1);
        cudaLaunchKernelEx(&cfg, k_scanA, n);

        cfg.blockDim = dim3(128, 1, 1);
        cfg.gridDim  = dim3(1, 1, 1);
        cudaLaunchKernelEx(&cfg, k_scanB, nA);

        cfg.blockDim = dim3(SCAN_TB, 1, 1);
        cfg.gridDim  = dim3(nA, 1, 1);
        cudaLaunchKernelEx(&cfg, k_scanC, n);

        cfg.blockDim = dim3(TB, 1, 1);
        cfg.gridDim  = dim3(NSM * 8, 1, 1);
        cudaLaunchKernelEx(&cfg, k_place, row, col, E);

        cudaLaunchKernelEx(&cfg, k_hop<0>, E, n);
        cudaLaunchKernelEx(&cfg, k_hop<1>, E, n);
        cudaLaunchKernelEx(&cfg, k_hop<2>, E, n);

        cfg.gridDim = dim3(G, 1, 1);
        cudaLaunchKernelEx(&cfg, k_out, batch, b, (float*)d_out, n);
    }
}